// round 11
// baseline (speedup 1.0000x reference)
#include <cuda_runtime.h>
#include <cuda_bf16.h>

#define TT 20
#define NIMG 64
#define AMAX 9408
#define NT 1024
#define NBLK 192
// dynamic smem layout: bce[9408]f | info[9408]u8 | hcnt[2048]i | hsum[2048]f
#define OFF_INFO 37632
#define OFF_HCNT 47040
#define OFF_HSUM 55232
#define DSMEM    63424

__device__ float g_partial[NBLK * 3];
__device__ int g_ticket;

__device__ __forceinline__ float wsum(float v) {
#pragma unroll
    for (int o = 16; o; o >>= 1) v += __shfl_down_sync(0xffffffffu, v, o);
    return v;
}
__device__ __forceinline__ int wsumi(int v) {
#pragma unroll
    for (int o = 16; o; o >>= 1) v += __shfl_down_sync(0xffffffffu, v, o);
    return v;
}

__global__ __launch_bounds__(NT, 1) void fused_loss(
    const float* __restrict__ p0, const float* __restrict__ p1, const float* __restrict__ p2,
    const float* __restrict__ tb, const int* __restrict__ tl, float* __restrict__ out)
{
    extern __shared__ __align__(16) char dsm[];
    float* const s_bce = reinterpret_cast<float*>(dsm);
    unsigned char* const s_info = reinterpret_cast<unsigned char*>(dsm + OFF_INFO);
    int* const s_hcnt = reinterpret_cast<int*>(dsm + OFF_HCNT);
    float* const s_hsum = reinterpret_cast<float*>(dsm + OFF_HSUM);

    __shared__ float4 sbox[TT];
    __shared__ float sarea[TT];
    __shared__ int slab[TT];
    __shared__ unsigned long long s_best[TT];
    __shared__ unsigned s_aidx[TT];
    __shared__ float s_facc[4];          // pos_bce, cls, loc, sum_higher
    __shared__ int s_cnt[4];
    __shared__ int s_ws[32];
    __shared__ int s_selbin, s_Sless;
    __shared__ int s_flag;

    const int bid = blockIdx.x;               // 0..63 s0, 64..127 s1, 128..191 s2
    const int s = (bid < 64) ? 0 : (bid < 128) ? 1 : 2;
    const int b = bid & 63;
    const int f   = 56 >> s;
    const int HW  = f * f;
    const int A   = HW * 3;
    const float strd = (float)(8 << s);
    const float w0 = (float)(16 << s), w1 = (float)(20 << s), w2 = (float)(24 << s);
    const float hw0 = 0.5f * w0, hw1 = 0.5f * w1, hw2 = 0.5f * w2;
    const float aa0 = w0 * w0, aa1 = w1 * w1, aa2 = w2 * w2;
    const float hmax = (float)(12 << s);
    const float* pred = ((s == 0) ? p0 : (s == 1) ? p1 : p2) + (size_t)b * 24 * HW;
    const int tid = threadIdx.x;
    const int lane = tid & 31, wid = tid >> 5;

    if (tid < TT) {
        const float* bp = tb + (b * TT + tid) * 4;
        const float4 g = make_float4(bp[0], bp[1], bp[2], bp[3]);
        sbox[tid] = g;
        sarea[tid] = (g.z - g.x) * (g.w - g.y);
        slab[tid] = tl[b * TT + tid];
        s_best[tid] = 0ull;
    }
    if (tid < 4) { s_facc[tid] = 0.f; s_cnt[tid] = 0; }
    for (int i = tid; i < 2048; i += NT) { s_hcnt[i] = 0; s_hsum[i] = 0.f; }
    __syncthreads();

    // ================= Matching + BCE (pixel-centric: 3 anchors/thread) ==
    for (int base = wid * 32; base < HW; base += NT) {
        const int pix = base + lane;
        const bool valid = pix < HW;
        const int cpix = valid ? pix : (HW - 1);
        const int gy = cpix / f;
        const int gx = cpix - gy * f;
        const float cx = ((float)gx + 0.5f) * strd;
        const float cy = ((float)gy + 0.5f) * strd;

        // analytic warp band (32 consecutive pixels), padded by max half-size
        const int p_hi = min(base + 31, HW - 1);
        const int gy0 = base / f, gy1 = p_hi / f;
        int gx0, gx1;
        if (gy0 == gy1) { gx0 = base - gy0 * f; gx1 = p_hi - gy1 * f; }
        else            { gx0 = 0; gx1 = f - 1; }
        const float xl = ((float)gx0 + 0.5f) * strd - hmax;
        const float xh = ((float)gx1 + 0.5f) * strd + hmax;
        const float yl = ((float)gy0 + 0.5f) * strd - hmax;
        const float yh = ((float)gy1 + 0.5f) * strd + hmax;

        bool act = false;
        if (lane < TT) {
            const float4 g = sbox[lane];
            act = (g.z > xl) && (g.x < xh) && (g.w > yl) && (g.y < yh);
        }
        const unsigned mask = __ballot_sync(0xffffffffu, act);

        float mi0 = 0.f, mi1 = 0.f, mi2 = 0.f;
        int mt0 = 0, mt1 = 0, mt2 = 0;
        const unsigned i3 = (unsigned)(cpix * 3);
#pragma unroll
        for (int t = 0; t < TT; t++) {
            if (mask & (1u << t)) {
                const float4 g = sbox[t];
                const float ar = sarea[t];
                const unsigned long long sb = s_best[t];
                // a3 = 0
                {
                    const float iw = fminf(cx + hw0, g.z) - fmaxf(cx - hw0, g.x);
                    const float ih = fminf(cy + hw0, g.w) - fmaxf(cy - hw0, g.y);
                    const float inter = fmaxf(iw, 0.f) * fmaxf(ih, 0.f);
                    const float iou = __fdividef(inter, aa0 + ar - inter + 1e-9f);
                    if (iou > mi0) { mi0 = iou; mt0 = t; }
                    const unsigned long long pk =
                        ((unsigned long long)__float_as_uint(iou) << 32) | ~i3;
                    if (pk > sb) atomicMax(&s_best[t], pk);
                }
                // a3 = 1
                {
                    const float iw = fminf(cx + hw1, g.z) - fmaxf(cx - hw1, g.x);
                    const float ih = fminf(cy + hw1, g.w) - fmaxf(cy - hw1, g.y);
                    const float inter = fmaxf(iw, 0.f) * fmaxf(ih, 0.f);
                    const float iou = __fdividef(inter, aa1 + ar - inter + 1e-9f);
                    if (iou > mi1) { mi1 = iou; mt1 = t; }
                    const unsigned long long pk =
                        ((unsigned long long)__float_as_uint(iou) << 32) | ~(i3 + 1u);
                    if (pk > sb) atomicMax(&s_best[t], pk);
                }
                // a3 = 2
                {
                    const float iw = fminf(cx + hw2, g.z) - fmaxf(cx - hw2, g.x);
                    const float ih = fminf(cy + hw2, g.w) - fmaxf(cy - hw2, g.y);
                    const float inter = fmaxf(iw, 0.f) * fmaxf(ih, 0.f);
                    const float iou = __fdividef(inter, aa2 + ar - inter + 1e-9f);
                    if (iou > mi2) { mi2 = iou; mt2 = t; }
                    const unsigned long long pk =
                        ((unsigned long long)__float_as_uint(iou) << 32) | ~(i3 + 2u);
                    if (pk > sb) atomicMax(&s_best[t], pk);
                }
            }
        }
        if (valid) {
            const float* p4 = pred + 4 * HW + pix;
            const float x0 = __ldg(p4);
            const float x1 = __ldg(p4 + 8 * HW);
            const float x2 = __ldg(p4 + 16 * HW);
            const bool q0 = mi0 >= 0.5f, q1 = mi1 >= 0.5f, q2 = mi2 >= 0.5f;
            s_bce[i3 + 0] = fmaxf(x0, 0.f) - (q0 ? x0 : 0.f) + log1pf(__expf(-fabsf(x0)));
            s_bce[i3 + 1] = fmaxf(x1, 0.f) - (q1 ? x1 : 0.f) + log1pf(__expf(-fabsf(x1)));
            s_bce[i3 + 2] = fmaxf(x2, 0.f) - (q2 ? x2 : 0.f) + log1pf(__expf(-fabsf(x2)));
            s_info[i3 + 0] = (unsigned char)(mt0 | (q0 ? 64 : 0) | (mi0 < 0.3f ? 128 : 0));
            s_info[i3 + 1] = (unsigned char)(mt1 | (q1 ? 64 : 0) | (mi1 < 0.3f ? 128 : 0));
            s_info[i3 + 2] = (unsigned char)(mt2 | (q2 ? 64 : 0) | (mi2 < 0.3f ? 128 : 0));
        }
    }
    __syncthreads();

    // ================= Forced-match overrides (parallel, last-t wins) ====
    if (wid == 0) {
        const bool has = lane < TT;
        unsigned aidx = 0;
        if (has) {
            const unsigned long long v = s_best[lane];
            aidx = ~(unsigned)(v & 0xFFFFFFFFull);
            s_aidx[lane] = aidx;
        }
        __syncwarp();
        bool win = has;
        if (has) {
            for (int t2 = lane + 1; t2 < TT; t2++)
                if (s_aidx[t2] == aidx) win = false;
        }
        if (win) {
            const unsigned old = s_info[aidx];
            if (!(old & 64u)) {                 // newly positive: bce(y=0) -> bce(y=1)
                const int pix = aidx / 3, a3 = aidx - pix * 3;
                s_bce[aidx] -= __ldg(pred + (a3 * 8 + 4) * HW + pix);
            }
            s_info[aidx] = (unsigned char)(lane | 64u);
        }
    }
    __syncthreads();

    // ================= Epilogue scan (+ fused level-1 hists) =============
    // Non-negative keys clobbered to 0; count+sum hist on bits[21:32).
    float pos_bce = 0.f, cls_sum = 0.f, loc_sum = 0.f;
    int pos_cnt = 0, neg_cnt = 0;
    for (int idx = tid; idx < A; idx += NT) {
        const unsigned info = s_info[idx];
        float key;
        if (info & 128u) { neg_cnt++; key = s_bce[idx]; }
        else {
            const float bv = s_bce[idx];
            s_bce[idx] = 0.0f;
            key = 0.0f;
            if (info & 64u) {
                pos_cnt++;
                pos_bce += bv;
                const int mt = info & 31u;
                const int pix = idx / 3, a3 = idx - pix * 3;
                const float* pp = pred + a3 * 8 * HW + pix;
                const float c0 = pp[5 * HW], c1 = pp[6 * HW], c2 = pp[7 * HW];
                const float m = fmaxf(c0, fmaxf(c1, c2));
                const float lse = m + __logf(__expf(c0 - m) + __expf(c1 - m) + __expf(c2 - m));
                const int tgt = slab[mt] - 1;
                const float ct = (tgt == 0) ? c0 : (tgt == 1) ? c1 : c2;
                cls_sum += lse - ct;

                const int gy = pix / f;
                const int gx = pix - gy * f;
                const float cx = ((float)gx + 0.5f) * strd;
                const float cy = ((float)gy + 0.5f) * strd;
                const float w = (a3 == 0) ? w0 : (a3 == 1) ? w1 : w2;
                const float4 g = sbox[mt];
                const float gw = g.z - g.x, gh = g.w - g.y;
                const float gcx = (g.x + g.z) * 0.5f, gcy = (g.y + g.w) * 0.5f;
                const float td0 = __fdividef(gcx - cx, w);
                const float td1 = __fdividef(gcy - cy, w);
                const float td2 = __logf(__fdividef(gw, w));
                const float td3 = __logf(__fdividef(gh, w));
                const float d0 = fabsf(pp[0 * HW] - td0);
                const float d1 = fabsf(pp[1 * HW] - td1);
                const float d2 = fabsf(pp[2 * HW] - td2);
                const float d3 = fabsf(pp[3 * HW] - td3);
                loc_sum += (d0 < 1.f ? 0.5f * d0 * d0 : d0 - 0.5f)
                         + (d1 < 1.f ? 0.5f * d1 * d1 : d1 - 0.5f)
                         + (d2 < 1.f ? 0.5f * d2 * d2 : d2 - 0.5f)
                         + (d3 < 1.f ? 0.5f * d3 * d3 : d3 - 0.5f);
            }
        }
        const unsigned kb = __float_as_uint(key) >> 21;
        atomicAdd(&s_hcnt[kb], 1);
        atomicAdd(&s_hsum[kb], key);
    }
    pos_bce = wsum(pos_bce); cls_sum = wsum(cls_sum); loc_sum = wsum(loc_sum);
    pos_cnt = wsumi(pos_cnt); neg_cnt = wsumi(neg_cnt);
    if (lane == 0) {
        atomicAdd(&s_facc[0], pos_bce);
        atomicAdd(&s_facc[1], cls_sum);
        atomicAdd(&s_facc[2], loc_sum);
        atomicAdd(&s_cnt[0], pos_cnt);
        atomicAdd(&s_cnt[1], neg_cnt);
    }
    __syncthreads();
    const int num_pos = s_cnt[0];
    const int num_neg = s_cnt[1];
    const int need = min(3 * num_pos, num_neg);

    // ================= 3-level radix select with sum-histograms ==========
    // neg_sum = sum(keys > kval) + ties*kval, where sum(keys > kval) is
    // accumulated per level from hsum over strictly-higher bins.
    float neg_sum = 0.f;
    if (need > 0) {
        int kneed = need;
        unsigned prefix = 0;
        const int shv[3] = {21, 10, 0};
        const int wv[3]  = {11, 11, 10};
#pragma unroll
        for (int p = 0; p < 3; p++) {
            const int sh = shv[p], w = wv[p];
            const int nb = 1 << w;              // 2048, 2048, 1024
            const int gpt = nb >> 10;           // 2, 2, 1
            if (p > 0) {
                for (int i = tid; i < nb; i += NT) { s_hcnt[i] = 0; s_hsum[i] = 0.f; }
                __syncthreads();
                for (int idx = tid; idx < A; idx += NT) {
                    const float vv = s_bce[idx];
                    const unsigned bits = __float_as_uint(vv);
                    if ((bits >> (sh + w)) == prefix) {
                        const unsigned bin = (bits >> sh) & (nb - 1);
                        atomicAdd(&s_hcnt[bin], 1);
                        atomicAdd(&s_hsum[bin], vv);
                    }
                }
                __syncthreads();
            }
            // pick bin via block suffix scan of counts
            const int bbase = tid * gpt;
            int h[2]; int local = 0;
#pragma unroll
            for (int j = 0; j < 2; j++) {
                h[j] = (j < gpt && bbase + j < nb) ? s_hcnt[bbase + j] : 0;
                local += h[j];
            }
            int v = local;
#pragma unroll
            for (int o = 1; o < 32; o <<= 1) {
                const int u = __shfl_down_sync(0xffffffffu, v, o);
                if (lane + o < 32) v += u;
            }
            if (lane == 0) s_ws[wid] = v;
            __syncthreads();
            if (tid < 32) {
                int x = s_ws[tid];
#pragma unroll
                for (int o = 1; o < 32; o <<= 1) {
                    const int u = __shfl_down_sync(0xffffffffu, x, o);
                    if (tid + o < 32) x += u;
                }
                s_ws[tid] = x;                   // inclusive suffix of warp sums
            }
            __syncthreads();
            int suf = (v - local) + ((wid < 31) ? s_ws[wid + 1] : 0);
#pragma unroll
            for (int j = 1; j >= 0; j--) {
                if (j < gpt && bbase + j < nb) {
                    if (suf < kneed && kneed <= suf + h[j]) { s_selbin = bbase + j; s_Sless = suf; }
                    suf += h[j];
                }
            }
            __syncthreads();
            // accumulate sum of strictly-higher bins at this level
            float shs = 0.f;
            for (int i = tid; i < nb; i += NT)
                if (i > s_selbin) shs += s_hsum[i];
            shs = wsum(shs);
            if (lane == 0) atomicAdd(&s_facc[3], shs);
            kneed -= s_Sless;
            prefix = (prefix << w) | (unsigned)s_selbin;
            __syncthreads();
        }
        neg_sum = s_facc[3] + (float)kneed * __uint_as_float(prefix);
    }

    if (tid == 0) {
        const float obj_loss = (s_facc[0] + neg_sum) / (float)max(num_pos + need, 1);
        const float cls_loss = s_facc[1] / (float)max(num_pos, 1);
        const float loc_loss = s_facc[2] / (float)max(4 * num_pos, 1);
        g_partial[bid * 3 + 0] = obj_loss;
        g_partial[bid * 3 + 1] = cls_loss;
        g_partial[bid * 3 + 2] = loc_loss;
    }

    // ================= Last-block finalize ================================
    __threadfence();
    if (tid == 0) {
        const int t = atomicAdd(&g_ticket, 1);
        s_flag = (t == NBLK - 1);
    }
    __syncthreads();
    if (s_flag && tid < 32) {
        float o = 0.f, c = 0.f, l = 0.f;
        for (int i = tid; i < NBLK; i += 32) {
            o += g_partial[3 * i + 0];
            c += g_partial[3 * i + 1];
            l += g_partial[3 * i + 2];
        }
        o = wsum(o); c = wsum(c); l = wsum(l);
        if (tid == 0) {
            g_ticket = 0;                        // self-reset for next replay
            o *= (1.f / 64.f); c *= (1.f / 64.f); l *= (1.f / 64.f);
            out[0] = o; out[1] = c; out[2] = l; out[3] = o + c + 2.f * l;
        }
    }
}

extern "C" void kernel_launch(void* const* d_in, const int* in_sizes, int n_in,
                              void* d_out, int out_size) {
    const float* p0 = (const float*)d_in[0];
    const float* p1 = (const float*)d_in[1];
    const float* p2 = (const float*)d_in[2];
    const float* tb = (const float*)d_in[6];
    const int*   tl = (const int*)d_in[7];

    cudaFuncSetAttribute((const void*)fused_loss,
                         cudaFuncAttributeMaxDynamicSharedMemorySize, DSMEM);
    fused_loss<<<NBLK, NT, DSMEM>>>(p0, p1, p2, tb, tl, (float*)d_out);
}

// round 12
// speedup vs baseline: 1.5673x; 1.5673x over previous
#include <cuda_runtime.h>
#include <cuda_bf16.h>

#define TT 20
#define NIMG 64
#define AMAX 9408
#define NT 1024
#define NBLK 192
// dynamic smem: bce[9408]f | info[9408]u8 | hcnt[2048]i
#define OFF_INFO 37632
#define OFF_HCNT 47040
#define DSMEM    55232

__device__ float g_partial[NBLK * 3];
__device__ int g_ticket;

__device__ __forceinline__ float wsum(float v) {
#pragma unroll
    for (int o = 16; o; o >>= 1) v += __shfl_down_sync(0xffffffffu, v, o);
    return v;
}
__device__ __forceinline__ int wsumi(int v) {
#pragma unroll
    for (int o = 16; o; o >>= 1) v += __shfl_down_sync(0xffffffffu, v, o);
    return v;
}

__global__ __launch_bounds__(NT, 1) void fused_loss(
    const float* __restrict__ p0, const float* __restrict__ p1, const float* __restrict__ p2,
    const float* __restrict__ tb, const int* __restrict__ tl, float* __restrict__ out)
{
    extern __shared__ __align__(16) char dsm[];
    float* const s_bce = reinterpret_cast<float*>(dsm);
    unsigned char* const s_info = reinterpret_cast<unsigned char*>(dsm + OFF_INFO);
    int* const s_hist = reinterpret_cast<int*>(dsm + OFF_HCNT);

    __shared__ float4 sbox[TT];
    __shared__ float sarea[TT];
    __shared__ int slab[TT];
    __shared__ unsigned long long s_best[TT];
    __shared__ unsigned s_aidx[TT];
    __shared__ float s_facc[4];
    __shared__ int s_cnt[4];
    __shared__ int s_ws[32];
    __shared__ int s_selbin, s_Sless;
    __shared__ int s_flag;

    const int bid = blockIdx.x;               // 0..63 s0, 64..127 s1, 128..191 s2
    const int s = (bid < 64) ? 0 : (bid < 128) ? 1 : 2;
    const int b = bid & 63;
    const int f   = 56 >> s;
    const int HW  = f * f;
    const int A   = HW * 3;
    const int shf = 3 - s;                    // f = 7 << shf
    const float strd = (float)(8 << s);
    const float w0 = (float)(16 << s), w1 = (float)(20 << s), w2 = (float)(24 << s);
    const float hmax = (float)(12 << s);
    const float* pred = ((s == 0) ? p0 : (s == 1) ? p1 : p2) + (size_t)b * 24 * HW;
    const int tid = threadIdx.x;
    const int lane = tid & 31, wid = tid >> 5;

    if (tid < TT) {
        const float* bp = tb + (b * TT + tid) * 4;
        const float4 g = make_float4(bp[0], bp[1], bp[2], bp[3]);
        sbox[tid] = g;
        sarea[tid] = (g.z - g.x) * (g.w - g.y);
        slab[tid] = tl[b * TT + tid];
        s_best[tid] = 0ull;
    }
    if (tid < 4) { s_facc[tid] = 0.f; s_cnt[tid] = 0; }
    for (int i = tid; i < 2048; i += NT) s_hist[i] = 0;
    __syncthreads();

    // ================= Matching + BCE (anchor-centric, R10 baseline) =====
    for (int base = wid * 32; base < A; base += NT) {
        const int idx = base + lane;
        const bool valid = idx < A;
        const int cidx = valid ? idx : (A - 1);
        const int pix = cidx / 3;
        const int a3  = cidx - pix * 3;
        const int q   = pix >> shf;
        const int gy  = q / 7;
        const int gx  = pix - gy * f;
        const float cx = ((float)gx + 0.5f) * strd;
        const float cy = ((float)gy + 0.5f) * strd;
        const float w  = (a3 == 0) ? w0 : (a3 == 1) ? w1 : w2;
        const float h2 = 0.5f * w;
        const float ax1 = cx - h2, ay1 = cy - h2, ax2 = cx + h2, ay2 = cy + h2;
        const float areaA = w * w;

        // analytic warp bounding band
        const int p_lo = base / 3;
        const int p_hi = min(base + 31, A - 1) / 3;
        const int gy0 = (p_lo >> shf) / 7;
        const int gy1 = (p_hi >> shf) / 7;
        int gx0, gx1;
        if (gy0 == gy1) { gx0 = p_lo - gy0 * f; gx1 = p_hi - gy1 * f; }
        else            { gx0 = 0; gx1 = f - 1; }
        const float xl = ((float)gx0 + 0.5f) * strd - hmax;
        const float xh = ((float)gx1 + 0.5f) * strd + hmax;
        const float yl = ((float)gy0 + 0.5f) * strd - hmax;
        const float yh = ((float)gy1 + 0.5f) * strd + hmax;

        bool act = false;
        if (lane < TT) {
            const float4 g = sbox[lane];
            act = (g.z > xl) && (g.x < xh) && (g.w > yl) && (g.y < yh);
        }
        const unsigned mask = __ballot_sync(0xffffffffu, act);

        float maxiou = 0.f; int mt = 0;
        const unsigned nidx = ~(unsigned)cidx;
#pragma unroll
        for (int t = 0; t < TT; t++) {
            if (mask & (1u << t)) {
                const float4 g = sbox[t];
                const float iw = fminf(ax2, g.z) - fmaxf(ax1, g.x);
                const float ih = fminf(ay2, g.w) - fmaxf(ay1, g.y);
                const float inter = fmaxf(iw, 0.f) * fmaxf(ih, 0.f);
                const float uni = areaA + sarea[t] - inter + 1e-9f;
                const float iou = __fdividef(inter, uni);
                if (iou > maxiou) { maxiou = iou; mt = t; }   // first-index tie-break
                const unsigned long long pk =
                    ((unsigned long long)__float_as_uint(iou) << 32) | nidx;
                if (pk > s_best[t]) atomicMax(&s_best[t], pk);  // monotone, re-checked atomically
            }
        }
        if (valid) {
            unsigned info = (unsigned)mt;
            const bool pos = maxiou >= 0.5f;
            if (pos) info |= 64u;
            if (maxiou < 0.3f) info |= 128u;
            const float x = __ldg(pred + (a3 * 8 + 4) * HW + pix);
            const float bce = fmaxf(x, 0.f) - (pos ? x : 0.f) + log1pf(__expf(-fabsf(x)));
            s_bce[idx]  = bce;
            s_info[idx] = (unsigned char)info;
        }
    }
    __syncthreads();

    // ================= Forced-match overrides (parallel, last-t wins) ====
    if (wid == 0) {
        const bool has = lane < TT;
        unsigned aidx = 0;
        if (has) {
            const unsigned long long v = s_best[lane];
            aidx = ~(unsigned)(v & 0xFFFFFFFFull);
            s_aidx[lane] = aidx;
        }
        __syncwarp();
        bool win = has;
        if (has) {
            for (int t2 = lane + 1; t2 < TT; t2++)
                if (s_aidx[t2] == aidx) win = false;
        }
        if (win) {
            const unsigned old = s_info[aidx];
            if (!(old & 64u)) {                 // newly positive: bce(y=0) -> bce(y=1)
                const int pix = aidx / 3, a3 = aidx - pix * 3;
                s_bce[aidx] -= __ldg(pred + (a3 * 8 + 4) * HW + pix);
            }
            s_info[aidx] = (unsigned char)(lane | 64u);
        }
    }
    __syncthreads();

    // ================= Epilogue (+ fused, warp-aggregated p0 hist) =======
    // Non-negative keys clobbered to 0 (never selectable: all true negative
    // BCEs are strictly positive). Count-hist on bits[21:32), zeros skipped.
    float pos_bce = 0.f, cls_sum = 0.f, loc_sum = 0.f;
    int pos_cnt = 0, neg_cnt = 0;
    for (int idx = tid; idx < A; idx += NT) {
        const unsigned info = s_info[idx];
        float key = 0.f;
        if (info & 128u) { neg_cnt++; key = s_bce[idx]; }
        else {
            const float bv = s_bce[idx];
            s_bce[idx] = 0.0f;
            if (info & 64u) {
                pos_cnt++;
                pos_bce += bv;
                const int mt = info & 31u;
                const int pix = idx / 3, a3 = idx - pix * 3;
                const float* pp = pred + a3 * 8 * HW + pix;
                const float c0 = pp[5 * HW], c1 = pp[6 * HW], c2 = pp[7 * HW];
                const float m = fmaxf(c0, fmaxf(c1, c2));
                const float lse = m + __logf(__expf(c0 - m) + __expf(c1 - m) + __expf(c2 - m));
                const int tgt = slab[mt] - 1;
                const float ct = (tgt == 0) ? c0 : (tgt == 1) ? c1 : c2;
                cls_sum += lse - ct;

                const int q = pix >> shf;
                const int gy = q / 7;
                const int gx = pix - gy * f;
                const float cx = ((float)gx + 0.5f) * strd;
                const float cy = ((float)gy + 0.5f) * strd;
                const float w = (a3 == 0) ? w0 : (a3 == 1) ? w1 : w2;
                const float4 g = sbox[mt];
                const float gw = g.z - g.x, gh = g.w - g.y;
                const float gcx = (g.x + g.z) * 0.5f, gcy = (g.y + g.w) * 0.5f;
                const float td0 = __fdividef(gcx - cx, w);
                const float td1 = __fdividef(gcy - cy, w);
                const float td2 = __logf(__fdividef(gw, w));
                const float td3 = __logf(__fdividef(gh, w));
                const float d0 = fabsf(pp[0 * HW] - td0);
                const float d1 = fabsf(pp[1 * HW] - td1);
                const float d2 = fabsf(pp[2 * HW] - td2);
                const float d3 = fabsf(pp[3 * HW] - td3);
                loc_sum += (d0 < 1.f ? 0.5f * d0 * d0 : d0 - 0.5f)
                         + (d1 < 1.f ? 0.5f * d1 * d1 : d1 - 0.5f)
                         + (d2 < 1.f ? 0.5f * d2 * d2 : d2 - 0.5f)
                         + (d3 < 1.f ? 0.5f * d3 * d3 : d3 - 0.5f);
            }
        }
        // warp-aggregated histogram add (leader per distinct bin)
        const unsigned am = __activemask();
        const unsigned bin = __float_as_uint(key) >> 21;   // 0 iff key == 0
        const unsigned grp = __match_any_sync(am, bin);
        if (bin != 0u && (__ffs(grp) - 1) == lane)
            atomicAdd(&s_hist[bin], __popc(grp));
    }
    pos_bce = wsum(pos_bce); cls_sum = wsum(cls_sum); loc_sum = wsum(loc_sum);
    pos_cnt = wsumi(pos_cnt); neg_cnt = wsumi(neg_cnt);
    if (lane == 0) {
        atomicAdd(&s_facc[0], pos_bce);
        atomicAdd(&s_facc[1], cls_sum);
        atomicAdd(&s_facc[2], loc_sum);
        atomicAdd(&s_cnt[0], pos_cnt);
        atomicAdd(&s_cnt[1], neg_cnt);
    }
    __syncthreads();
    const int num_pos = s_cnt[0];
    const int num_neg = s_cnt[1];
    const int need = min(3 * num_pos, num_neg);

    // ================= 3-pass radix select (need-th largest key) =========
    float neg_sum = 0.f;
    if (need > 0) {
        int kneed = need;
        unsigned prefix = 0;
        const int shv[3] = {21, 10, 0};
        const int wv[3]  = {11, 11, 10};
#pragma unroll
        for (int p = 0; p < 3; p++) {
            const int sh = shv[p], w = wv[p];
            const int nb = 1 << w;              // 2048, 2048, 1024
            const int gpt = (nb + NT - 1) / NT; // 2, 2, 1
            if (p > 0) {                        // p0 hist was fused into epilogue
                for (int i = tid; i < nb; i += NT) s_hist[i] = 0;
                __syncthreads();
                for (int idx = tid; idx < A; idx += NT) {
                    const unsigned bits = __float_as_uint(s_bce[idx]);
                    if ((bits >> (sh + w)) == prefix)
                        atomicAdd(&s_hist[(bits >> sh) & (nb - 1)], 1);
                }
                __syncthreads();
            }
            const int bbase = tid * gpt;
            int h[2]; int local = 0;
#pragma unroll
            for (int j = 0; j < 2; j++) {
                h[j] = (j < gpt && bbase + j < nb) ? s_hist[bbase + j] : 0;
                local += h[j];
            }
            int v = local;                       // inclusive suffix within warp
#pragma unroll
            for (int o = 1; o < 32; o <<= 1) {
                const int u = __shfl_down_sync(0xffffffffu, v, o);
                if (lane + o < 32) v += u;
            }
            if (lane == 0) s_ws[wid] = v;
            __syncthreads();
            if (tid < 32) {
                int x = s_ws[tid];
#pragma unroll
                for (int o = 1; o < 32; o <<= 1) {
                    const int u = __shfl_down_sync(0xffffffffu, x, o);
                    if (tid + o < 32) x += u;
                }
                s_ws[tid] = x;                   // inclusive suffix of warp sums
            }
            __syncthreads();
            int suf = (v - local) + ((wid < 31) ? s_ws[wid + 1] : 0);
#pragma unroll
            for (int j = 1; j >= 0; j--) {
                if (j < gpt && bbase + j < nb) {
                    if (suf < kneed && kneed <= suf + h[j]) { s_selbin = bbase + j; s_Sless = suf; }
                    suf += h[j];
                }
            }
            __syncthreads();
            kneed -= s_Sless;
            prefix = (prefix << w) | (unsigned)s_selbin;
            __syncthreads();
        }
        const unsigned kbits = prefix;           // bits of the need-th largest key
        int cgt = 0; float sgt = 0.f;
        for (int idx = tid; idx < A; idx += NT) {
            const float vv = s_bce[idx];
            if (__float_as_uint(vv) > kbits) { cgt++; sgt += vv; }
        }
        cgt = wsumi(cgt); sgt = wsum(sgt);
        if (lane == 0) { atomicAdd(&s_cnt[2], cgt); atomicAdd(&s_facc[3], sgt); }
        __syncthreads();
        neg_sum = s_facc[3] + (float)(need - s_cnt[2]) * __uint_as_float(kbits);
    }

    if (tid == 0) {
        const float obj_loss = (s_facc[0] + neg_sum) / (float)max(num_pos + need, 1);
        const float cls_loss = s_facc[1] / (float)max(num_pos, 1);
        const float loc_loss = s_facc[2] / (float)max(4 * num_pos, 1);
        g_partial[bid * 3 + 0] = obj_loss;
        g_partial[bid * 3 + 1] = cls_loss;
        g_partial[bid * 3 + 2] = loc_loss;
    }

    // ================= Last-block finalize ================================
    __threadfence();
    if (tid == 0) {
        const int t = atomicAdd(&g_ticket, 1);
        s_flag = (t == NBLK - 1);
    }
    __syncthreads();
    if (s_flag && tid < 32) {
        float o = 0.f, c = 0.f, l = 0.f;
        for (int i = tid; i < NBLK; i += 32) {
            o += g_partial[3 * i + 0];
            c += g_partial[3 * i + 1];
            l += g_partial[3 * i + 2];
        }
        o = wsum(o); c = wsum(c); l = wsum(l);
        if (tid == 0) {
            g_ticket = 0;                        // self-reset for next replay
            o *= (1.f / 64.f); c *= (1.f / 64.f); l *= (1.f / 64.f);
            out[0] = o; out[1] = c; out[2] = l; out[3] = o + c + 2.f * l;
        }
    }
}

extern "C" void kernel_launch(void* const* d_in, const int* in_sizes, int n_in,
                              void* d_out, int out_size) {
    const float* p0 = (const float*)d_in[0];
    const float* p1 = (const float*)d_in[1];
    const float* p2 = (const float*)d_in[2];
    const float* tb = (const float*)d_in[6];
    const int*   tl = (const int*)d_in[7];

    cudaFuncSetAttribute((const void*)fused_loss,
                         cudaFuncAttributeMaxDynamicSharedMemorySize, DSMEM);
    fused_loss<<<NBLK, NT, DSMEM>>>(p0, p1, p2, tb, tl, (float*)d_out);
}